// round 2
// baseline (speedup 1.0000x reference)
#include <cuda_runtime.h>
#include <cuda_bf16.h>
#include <math.h>

// Problem constants
#define CM 64        // channels / signal dim
#define NA 512       // dictionary atoms
#define MS 32768     // number of signals (8*64*64)
#define KS 5         // sparsity
#define HW 4096      // H*W
#define CHW 262144   // C*H*W
#define NUMEL 2097152.0f

// Device scratch (allocation-free requirement -> __device__ globals)
__device__ float g_DnT[NA * CM];     // [n][c] atom-major normalized dict
__device__ float g_Dn[CM * NA];      // [c][n] normalized dict
__device__ float g_G[NA * NA];       // Gram matrix
__device__ float g_H[(size_t)MS * NA]; // h_bar for every signal (64 MB)
__device__ float g_partial[8192];    // per-CTA squared-error partials

// ---------------------------------------------------------------------------
// Kernel 1: normalize dictionary columns, write both layouts
// ---------------------------------------------------------------------------
__global__ void k_norm(const float* __restrict__ dict) {
    int n = blockIdx.x * blockDim.x + threadIdx.x;
    if (n >= NA) return;
    float s = 0.f;
    #pragma unroll
    for (int c = 0; c < CM; c++) {
        float v = dict[c * NA + n];
        s += v * v;
    }
    float inv = 1.f / fmaxf(sqrtf(s), 1e-10f);
    #pragma unroll
    for (int c = 0; c < CM; c++) {
        float v = dict[c * NA + n] * inv;
        g_DnT[n * CM + c] = v;
        g_Dn[c * NA + n] = v;
    }
}

// ---------------------------------------------------------------------------
// Kernel 2: Gram matrix G = Dn^T Dn. One block per row i.
// ---------------------------------------------------------------------------
__global__ void k_gram() {
    __shared__ float di[CM];
    int i = blockIdx.x;
    if (threadIdx.x < CM / 4)
        ((float4*)di)[threadIdx.x] = ((const float4*)(g_DnT + i * CM))[threadIdx.x];
    __syncthreads();
    for (int j = threadIdx.x; j < NA; j += blockDim.x) {
        const float4* dj = (const float4*)(g_DnT + j * CM);
        float s = 0.f;
        #pragma unroll
        for (int c = 0; c < CM / 4; c++) {
            float4 v = dj[c];
            s += di[c * 4 + 0] * v.x + di[c * 4 + 1] * v.y
               + di[c * 4 + 2] * v.z + di[c * 4 + 3] * v.w;
        }
        g_G[(size_t)i * NA + j] = s;
    }
}

// ---------------------------------------------------------------------------
// Kernel 3: H[m][n] = sum_c X[m][c] * Dn[c][n]
// X[m][c] = z_e[b*CHW + c*HW + p], m = b*HW + p.
// 128x128x8 tiles, 256 threads, 8x8 register blocking.
// ---------------------------------------------------------------------------
__global__ __launch_bounds__(256, 2) void k_gemm(const float* __restrict__ ze) {
    __shared__ float As[8][128];
    __shared__ float Bs[8][128];
    int tx = threadIdx.x & 15, ty = threadIdx.x >> 4;
    int m0 = blockIdx.y * 128, n0 = blockIdx.x * 128;
    int bb = m0 >> 12;           // batch (tile never straddles a batch: 4096 % 128 == 0)
    int p0 = m0 & (HW - 1);
    const float* zb = ze + (size_t)bb * CHW + p0;

    float acc[8][8];
    #pragma unroll
    for (int i = 0; i < 8; i++)
        #pragma unroll
        for (int j = 0; j < 8; j++) acc[i][j] = 0.f;

    int lidx = threadIdx.x * 4;
    int lk = lidx >> 7;          // 0..7
    int lm = lidx & 127;

    for (int kk = 0; kk < CM; kk += 8) {
        float4 av = *(const float4*)(zb + (size_t)(kk + lk) * HW + lm);
        float4 bv = *(const float4*)(g_Dn + (size_t)(kk + lk) * NA + n0 + lm);
        *(float4*)&As[lk][lm] = av;
        *(float4*)&Bs[lk][lm] = bv;
        __syncthreads();
        #pragma unroll
        for (int k = 0; k < 8; k++) {
            float4 a0 = *(float4*)&As[k][ty * 8];
            float4 a1 = *(float4*)&As[k][ty * 8 + 4];
            float4 b0 = *(float4*)&Bs[k][tx * 8];
            float4 b1 = *(float4*)&Bs[k][tx * 8 + 4];
            float ar[8] = {a0.x, a0.y, a0.z, a0.w, a1.x, a1.y, a1.z, a1.w};
            float br[8] = {b0.x, b0.y, b0.z, b0.w, b1.x, b1.y, b1.z, b1.w};
            #pragma unroll
            for (int i = 0; i < 8; i++)
                #pragma unroll
                for (int j = 0; j < 8; j++)
                    acc[i][j] = fmaf(ar[i], br[j], acc[i][j]);
        }
        __syncthreads();
    }
    #pragma unroll
    for (int i = 0; i < 8; i++) {
        int m = m0 + ty * 8 + i;
        float* o = &g_H[(size_t)m * NA + n0 + tx * 8];
        *(float4*)o       = make_float4(acc[i][0], acc[i][1], acc[i][2], acc[i][3]);
        *(float4*)(o + 4) = make_float4(acc[i][4], acc[i][5], acc[i][6], acc[i][7]);
    }
}

// ---------------------------------------------------------------------------
// Kernel 4: OMP, one warp per signal, 4 signals per CTA (128 threads).
// smem: h[4][512], cached G-rows[4][4][512], small per-warp scratch.
// ---------------------------------------------------------------------------
#define SIG 4
__global__ __launch_bounds__(128, 4) void k_omp(const float* __restrict__ ze,
                                                float* __restrict__ out_zdl,
                                                float* __restrict__ out_sup,
                                                float* __restrict__ out_cf) {
    __shared__ float h[SIG][NA];           // current residual correlations
    __shared__ float rows[SIG][4][NA];     // cached G rows (5th never needed)
    __shared__ float S[SIG][32];           // [0..4]=gamma [5..9]=delta [10..24]=L [25..29]=h_sel
    __shared__ int   sel[SIG][KS];
    __shared__ float werr[SIG];

    int wid = threadIdx.x >> 5, lane = threadIdx.x & 31;
    int m = blockIdx.x * SIG + wid;

    float* hh = h[wid];
    const float* Hb = g_H + (size_t)m * NA;

    // load h_bar
    for (int i = lane; i < NA / 4; i += 32)
        ((float4*)hh)[i] = ((const float4*)Hb)[i];
    __syncwarp();

    int nsel = 0;
    for (int k = 1; k <= KS; k++) {
        // ---- warp argmax of |h| excluding selected (lowest index wins ties)
        float bv = -1.f;
        int bi = 1 << 30;
        for (int i = lane; i < NA; i += 32) {
            bool excl = false;
            for (int t = 0; t < nsel; t++) excl |= (sel[wid][t] == i);
            float v = excl ? -1.f : fabsf(hh[i]);
            if (v > bv || (v == bv && i < bi)) { bv = v; bi = i; }
        }
        #pragma unroll
        for (int off = 16; off; off >>= 1) {
            float ov = __shfl_down_sync(0xffffffffu, bv, off);
            int   oi = __shfl_down_sync(0xffffffffu, bi, off);
            if (ov > bv || (ov == bv && oi < bi)) { bv = ov; bi = oi; }
        }
        bi = __shfl_sync(0xffffffffu, bi, 0);

        // ---- lane 0: Cholesky update + cho_solve (k <= 5, scalar)
        if (lane == 0) {
            float* gam = &S[wid][0];
            float* dlt = &S[wid][5];
            float* L   = &S[wid][10];
            float* hs  = &S[wid][25];
            if (k > 1) {
                float w[4];
                float ww = 0.f;
                for (int i = 0; i < k - 1; i++) {
                    float a = g_G[(size_t)sel[wid][i] * NA + bi];
                    for (int j = 0; j < i; j++) a -= L[i * (i + 1) / 2 + j] * w[j];
                    w[i] = a / L[i * (i + 1) / 2 + i];
                    ww += w[i] * w[i];
                }
                int r = k - 1;
                for (int j = 0; j < r; j++) L[r * (r + 1) / 2 + j] = w[j];
                L[r * (r + 1) / 2 + r] = sqrtf(fmaxf(1.f - ww, 1e-12f));
            } else {
                L[0] = 1.f;
            }
            sel[wid][k - 1] = bi;
            for (int i = 0; i < k; i++) hs[i] = Hb[sel[wid][i]];
            // forward: L y = hs
            float y[KS];
            for (int i = 0; i < k; i++) {
                float a = hs[i];
                for (int j = 0; j < i; j++) a -= L[i * (i + 1) / 2 + j] * y[j];
                y[i] = a / L[i * (i + 1) / 2 + i];
            }
            // backward: L^T g = y
            float g2[KS];
            for (int i = k - 1; i >= 0; i--) {
                float a = y[i];
                for (int j = i + 1; j < k; j++) a -= L[j * (j + 1) / 2 + i] * g2[j];
                g2[i] = a / L[i * (i + 1) / 2 + i];
            }
            for (int i = 0; i < k; i++) {
                float old = (i < k - 1) ? gam[i] : 0.f;
                dlt[i] = g2[i] - old;
                gam[i] = g2[i];
            }
        }
        __syncwarp();
        nsel = k;

        // ---- incremental h update: h -= sum_t delta[t] * G[sel[t], :]
        if (k < KS) {
            const float* Gr = g_G + (size_t)bi * NA;
            float dg[4];
            for (int t = 0; t < k; t++) dg[t] = S[wid][5 + t];
            float* nr = rows[wid][k - 1];
            for (int i = lane; i < NA; i += 32) {
                float gv = Gr[i];
                nr[i] = gv;
                float a = dg[k - 1] * gv;
                for (int t = 0; t < k - 1; t++)
                    a = fmaf(dg[t], rows[wid][t][i], a);
                hh[i] -= a;
            }
            __syncwarp();
        }
    }
    __syncwarp();

    // ---- reconstruction, output, squared error
    int bb = m >> 12, p = m & (HW - 1);
    float err = 0.f;
    for (int c = lane; c < CM; c += 32) {
        float r = 0.f;
        #pragma unroll
        for (int t = 0; t < KS; t++)
            r = fmaf(S[wid][t], g_DnT[(size_t)sel[wid][t] * CM + c], r);
        size_t zi = (size_t)bb * CHW + (size_t)c * HW + p;
        float x = ze[zi];
        float d = r - x;
        err += d * d;
        out_zdl[zi] = r;
    }
    #pragma unroll
    for (int off = 16; off; off >>= 1)
        err += __shfl_down_sync(0xffffffffu, err, off);
    if (lane == 0) {
        werr[wid] = err;
        #pragma unroll
        for (int t = 0; t < KS; t++) {
            out_sup[(size_t)m * KS + t] = (float)sel[wid][t];
            out_cf[(size_t)m * KS + t]  = S[wid][t];
        }
    }
    __syncthreads();
    if (threadIdx.x == 0) {
        float s = 0.f;
        for (int t = 0; t < SIG; t++) s += werr[t];
        g_partial[blockIdx.x] = s;
    }
}

// ---------------------------------------------------------------------------
// Kernel 5: deterministic loss reduction. loss = 1.25 * MSE
// ---------------------------------------------------------------------------
__global__ void k_loss(float* __restrict__ out_loss) {
    __shared__ float red[256];
    float s = 0.f;
    for (int i = threadIdx.x; i < 8192; i += 256) s += g_partial[i];
    red[threadIdx.x] = s;
    __syncthreads();
    for (int o = 128; o; o >>= 1) {
        if (threadIdx.x < o) red[threadIdx.x] += red[threadIdx.x + o];
        __syncthreads();
    }
    if (threadIdx.x == 0) out_loss[0] = 1.25f * red[0] / NUMEL;
}

// ---------------------------------------------------------------------------
extern "C" void kernel_launch(void* const* d_in, const int* in_sizes, int n_in,
                              void* d_out, int out_size) {
    const float* ze   = (const float*)d_in[0];  // [8,64,64,64]
    const float* dict = (const float*)d_in[1];  // [64,512]
    float* out = (float*)d_out;
    // output layout: z_dl (2097152) | loss (1) | support (163840) | coeffs (163840)
    float* out_zdl  = out;
    float* out_loss = out + 2097152;
    float* out_sup  = out + 2097153;
    float* out_cf   = out + 2097153 + 163840;

    k_norm<<<2, 256>>>(dict);
    k_gram<<<NA, 128>>>();
    dim3 g(NA / 128, MS / 128);
    k_gemm<<<g, 256>>>(ze);
    k_omp<<<MS / SIG, 128>>>(ze, out_zdl, out_sup, out_cf);
    k_loss<<<1, 256>>>(out_loss);
}

// round 3
// speedup vs baseline: 1.6496x; 1.6496x over previous
#include <cuda_runtime.h>
#include <cuda_bf16.h>
#include <math.h>

// Problem constants
#define CM 64        // channels / signal dim
#define NA 512       // dictionary atoms
#define MS 32768     // number of signals (8*64*64)
#define KS 5         // sparsity
#define HW 4096      // H*W
#define CHW 262144   // C*H*W
#define NUMEL 2097152.0f

// Device scratch (allocation-free requirement -> __device__ globals)
__device__ float g_DnT[NA * CM];     // [n][c] atom-major normalized dict
__device__ float g_Dn[CM * NA];      // [c][n] normalized dict
__device__ float g_G[NA * NA];       // Gram matrix
__device__ float g_H[(size_t)MS * NA]; // h_bar for every signal (64 MB)
__device__ float g_partial[8192];    // per-CTA squared-error partials

// ---------------------------------------------------------------------------
// Kernel 1: normalize dictionary columns, write both layouts
// ---------------------------------------------------------------------------
__global__ void k_norm(const float* __restrict__ dict) {
    int n = blockIdx.x * blockDim.x + threadIdx.x;
    if (n >= NA) return;
    float s = 0.f;
    #pragma unroll
    for (int c = 0; c < CM; c++) {
        float v = dict[c * NA + n];
        s += v * v;
    }
    float inv = 1.f / fmaxf(sqrtf(s), 1e-10f);
    #pragma unroll
    for (int c = 0; c < CM; c++) {
        float v = dict[c * NA + n] * inv;
        g_DnT[n * CM + c] = v;
        g_Dn[c * NA + n] = v;
    }
}

// ---------------------------------------------------------------------------
// Kernel 2: Gram matrix G = Dn^T Dn. One block per row i.
// ---------------------------------------------------------------------------
__global__ void k_gram() {
    __shared__ float di[CM];
    int i = blockIdx.x;
    if (threadIdx.x < CM / 4)
        ((float4*)di)[threadIdx.x] = ((const float4*)(g_DnT + i * CM))[threadIdx.x];
    __syncthreads();
    for (int j = threadIdx.x; j < NA; j += blockDim.x) {
        const float4* dj = (const float4*)(g_DnT + j * CM);
        float s = 0.f;
        #pragma unroll
        for (int c = 0; c < CM / 4; c++) {
            float4 v = dj[c];
            s += di[c * 4 + 0] * v.x + di[c * 4 + 1] * v.y
               + di[c * 4 + 2] * v.z + di[c * 4 + 3] * v.w;
        }
        g_G[(size_t)i * NA + j] = s;
    }
}

// ---------------------------------------------------------------------------
// Kernel 3: H[m][n] = sum_c X[m][c] * Dn[c][n]
// 128x128x8 tiles, 256 threads, 8x8 register blocking.
// ---------------------------------------------------------------------------
__global__ __launch_bounds__(256, 2) void k_gemm(const float* __restrict__ ze) {
    __shared__ float As[8][128];
    __shared__ float Bs[8][128];
    int tx = threadIdx.x & 15, ty = threadIdx.x >> 4;
    int m0 = blockIdx.y * 128, n0 = blockIdx.x * 128;
    int bb = m0 >> 12;
    int p0 = m0 & (HW - 1);
    const float* zb = ze + (size_t)bb * CHW + p0;

    float acc[8][8];
    #pragma unroll
    for (int i = 0; i < 8; i++)
        #pragma unroll
        for (int j = 0; j < 8; j++) acc[i][j] = 0.f;

    int lidx = threadIdx.x * 4;
    int lk = lidx >> 7;
    int lm = lidx & 127;

    for (int kk = 0; kk < CM; kk += 8) {
        float4 av = *(const float4*)(zb + (size_t)(kk + lk) * HW + lm);
        float4 bv = *(const float4*)(g_Dn + (size_t)(kk + lk) * NA + n0 + lm);
        *(float4*)&As[lk][lm] = av;
        *(float4*)&Bs[lk][lm] = bv;
        __syncthreads();
        #pragma unroll
        for (int k = 0; k < 8; k++) {
            float4 a0 = *(float4*)&As[k][ty * 8];
            float4 a1 = *(float4*)&As[k][ty * 8 + 4];
            float4 b0 = *(float4*)&Bs[k][tx * 8];
            float4 b1 = *(float4*)&Bs[k][tx * 8 + 4];
            float ar[8] = {a0.x, a0.y, a0.z, a0.w, a1.x, a1.y, a1.z, a1.w};
            float br[8] = {b0.x, b0.y, b0.z, b0.w, b1.x, b1.y, b1.z, b1.w};
            #pragma unroll
            for (int i = 0; i < 8; i++)
                #pragma unroll
                for (int j = 0; j < 8; j++)
                    acc[i][j] = fmaf(ar[i], br[j], acc[i][j]);
        }
        __syncthreads();
    }
    #pragma unroll
    for (int i = 0; i < 8; i++) {
        int m = m0 + ty * 8 + i;
        float* o = &g_H[(size_t)m * NA + n0 + tx * 8];
        *(float4*)o       = make_float4(acc[i][0], acc[i][1], acc[i][2], acc[i][3]);
        *(float4*)(o + 4) = make_float4(acc[i][4], acc[i][5], acc[i][6], acc[i][7]);
    }
}

// ---------------------------------------------------------------------------
// Kernel 4: OMP selection + coefficients. One warp per signal, 4 per CTA.
// All lane-0 solver state comes from smem (rows cache) + ONE L2 load per iter.
// Selected entries of h are zeroed (== reference mask semantics).
// ---------------------------------------------------------------------------
#define SIG 4
__global__ __launch_bounds__(128, 4) void k_omp(float* __restrict__ out_sup,
                                                float* __restrict__ out_cf) {
    __shared__ float h[SIG][NA];
    __shared__ float rows[SIG][4][NA];
    __shared__ float S[SIG][32];   // [0..4]=gamma [5..9]=delta [10..24]=L [25..29]=h_sel
    __shared__ int   sel[SIG][KS];

    int wid = threadIdx.x >> 5, lane = threadIdx.x & 31;
    int m = blockIdx.x * SIG + wid;

    float*  hh  = h[wid];
    float4* hh4 = (float4*)hh;
    const float* Hb = g_H + (size_t)m * NA;

    #pragma unroll
    for (int i = lane; i < NA / 4; i += 32)
        hh4[i] = ((const float4*)Hb)[i];
    __syncwarp();

    for (int k = 1; k <= KS; k++) {
        // ---- branch-light warp argmax of |h| (selected entries are 0)
        float bv = -1.f;
        int bi = 0;
        #pragma unroll
        for (int i = lane; i < NA; i += 32) {
            float v = fabsf(hh[i]);
            if (v > bv || (v == bv && i < bi)) { bv = v; bi = i; }
        }
        #pragma unroll
        for (int off = 16; off; off >>= 1) {
            float ov = __shfl_down_sync(0xffffffffu, bv, off);
            int   oi = __shfl_down_sync(0xffffffffu, bi, off);
            if (ov > bv || (ov == bv && oi < bi)) { bv = ov; bi = oi; }
        }
        bi = __shfl_sync(0xffffffffu, bi, 0);

        // ---- lane 0: Cholesky update + cho_solve (k <= 5).
        // G[sel_i][bi] comes from the smem rows cache; only h_bar[bi] is loaded.
        if (lane == 0) {
            float* gam = &S[wid][0];
            float* dlt = &S[wid][5];
            float* L   = &S[wid][10];
            float* hs  = &S[wid][25];
            if (k > 1) {
                float w[4];
                float ww = 0.f;
                for (int i = 0; i < k - 1; i++) {
                    float a = rows[wid][i][bi];
                    for (int j = 0; j < i; j++) a -= L[i * (i + 1) / 2 + j] * w[j];
                    w[i] = a / L[i * (i + 1) / 2 + i];
                    ww += w[i] * w[i];
                }
                int r = k - 1;
                for (int j = 0; j < r; j++) L[r * (r + 1) / 2 + j] = w[j];
                L[r * (r + 1) / 2 + r] = sqrtf(fmaxf(1.f - ww, 1e-12f));
            } else {
                L[0] = 1.f;
            }
            sel[wid][k - 1] = bi;
            hs[k - 1] = Hb[bi];          // single new h_bar value (L2-hot)
            // forward: L y = hs
            float y[KS];
            for (int i = 0; i < k; i++) {
                float a = hs[i];
                for (int j = 0; j < i; j++) a -= L[i * (i + 1) / 2 + j] * y[j];
                y[i] = a / L[i * (i + 1) / 2 + i];
            }
            // backward: L^T g = y
            float g2[KS];
            for (int i = k - 1; i >= 0; i--) {
                float a = y[i];
                for (int j = i + 1; j < k; j++) a -= L[j * (j + 1) / 2 + i] * g2[j];
                g2[i] = a / L[i * (i + 1) / 2 + i];
            }
            for (int i = 0; i < k; i++) {
                float old = (i < k - 1) ? gam[i] : 0.f;
                dlt[i] = g2[i] - old;
                gam[i] = g2[i];
            }
        }
        __syncwarp();

        // ---- incremental h update: h -= sum_t delta[t] * G[sel[t], :]  (float4)
        if (k < KS) {
            const float4* Gr = (const float4*)(g_G + (size_t)bi * NA);
            float dg[4];
            #pragma unroll
            for (int t = 0; t < 4; t++) dg[t] = (t < k) ? S[wid][5 + t] : 0.f;
            float4* nr = (float4*)rows[wid][k - 1];
            #pragma unroll
            for (int i = lane; i < NA / 4; i += 32) {
                float4 gv = Gr[i];
                nr[i] = gv;
                float4 a;
                a.x = dg[k - 1] * gv.x; a.y = dg[k - 1] * gv.y;
                a.z = dg[k - 1] * gv.z; a.w = dg[k - 1] * gv.w;
                for (int t = 0; t < k - 1; t++) {
                    float4 rv = ((float4*)rows[wid][t])[i];
                    a.x = fmaf(dg[t], rv.x, a.x);
                    a.y = fmaf(dg[t], rv.y, a.y);
                    a.z = fmaf(dg[t], rv.z, a.z);
                    a.w = fmaf(dg[t], rv.w, a.w);
                }
                float4 hv = hh4[i];
                hv.x -= a.x; hv.y -= a.y; hv.z -= a.z; hv.w -= a.w;
                hh4[i] = hv;
            }
            __syncwarp();
            // mask selected atoms exactly like the reference
            if (lane == 0)
                for (int t = 0; t < k; t++) hh[sel[wid][t]] = 0.f;
            __syncwarp();
        }
    }

    // ---- outputs (reconstruction happens in k_recon)
    if (lane < KS) {
        out_sup[(size_t)m * KS + lane] = (float)sel[wid][lane];
        out_cf[(size_t)m * KS + lane]  = S[wid][lane];
    }
}

// ---------------------------------------------------------------------------
// Kernel 5: coalesced reconstruction + squared error.
// Block = 32 signals x 64 channels. Phase 1 computes with lane=channel
// (coalesced DnT reads), phase 2 writes with lane=pixel (coalesced gmem).
// ---------------------------------------------------------------------------
__global__ __launch_bounds__(256) void k_recon(const float* __restrict__ ze,
                                               const float* __restrict__ sup,
                                               const float* __restrict__ cf,
                                               float* __restrict__ out_zdl) {
    __shared__ float tile[CM][33];
    __shared__ float red[256];

    int m0 = blockIdx.x * 32;
    int b  = m0 >> 12;
    int p0 = m0 & (HW - 1);
    int wid = threadIdx.x >> 5, lane = threadIdx.x & 31;

    // phase 1: 8 warps x 4 signals each
    for (int s = wid; s < 32; s += 8) {
        int m = m0 + s;
        int   si[KS];
        float ci[KS];
        #pragma unroll
        for (int t = 0; t < KS; t++) {
            si[t] = (int)sup[(size_t)m * KS + t];
            ci[t] = cf[(size_t)m * KS + t];
        }
        #pragma unroll
        for (int half = 0; half < 2; half++) {
            int c = lane + 32 * half;
            float r = 0.f;
            #pragma unroll
            for (int t = 0; t < KS; t++)
                r = fmaf(ci[t], g_DnT[si[t] * CM + c], r);
            tile[c][s] = r;
        }
    }
    __syncthreads();

    // phase 2: lane = pixel -> fully coalesced gmem
    int p  = threadIdx.x & 31;
    int cb = threadIdx.x >> 5;
    float err = 0.f;
    #pragma unroll
    for (int j = 0; j < 8; j++) {
        int c = cb * 8 + j;
        size_t zi = (size_t)b * CHW + (size_t)c * HW + p0 + p;
        float r = tile[c][p];
        float x = ze[zi];
        float d = r - x;
        err += d * d;
        out_zdl[zi] = r;
    }
    red[threadIdx.x] = err;
    __syncthreads();
    for (int o = 128; o; o >>= 1) {
        if (threadIdx.x < o) red[threadIdx.x] += red[threadIdx.x + o];
        __syncthreads();
    }
    if (threadIdx.x == 0) g_partial[blockIdx.x] = red[0];
}

// ---------------------------------------------------------------------------
// Kernel 6: deterministic loss reduction. loss = 1.25 * MSE
// ---------------------------------------------------------------------------
__global__ void k_loss(float* __restrict__ out_loss) {
    __shared__ float red[256];
    float s = 0.f;
    for (int i = threadIdx.x; i < 1024; i += 256) s += g_partial[i];
    red[threadIdx.x] = s;
    __syncthreads();
    for (int o = 128; o; o >>= 1) {
        if (threadIdx.x < o) red[threadIdx.x] += red[threadIdx.x + o];
        __syncthreads();
    }
    if (threadIdx.x == 0) out_loss[0] = 1.25f * red[0] / NUMEL;
}

// ---------------------------------------------------------------------------
extern "C" void kernel_launch(void* const* d_in, const int* in_sizes, int n_in,
                              void* d_out, int out_size) {
    const float* ze   = (const float*)d_in[0];  // [8,64,64,64]
    const float* dict = (const float*)d_in[1];  // [64,512]
    float* out = (float*)d_out;
    // output layout: z_dl (2097152) | loss (1) | support (163840) | coeffs (163840)
    float* out_zdl  = out;
    float* out_loss = out + 2097152;
    float* out_sup  = out + 2097153;
    float* out_cf   = out + 2097153 + 163840;

    k_norm<<<2, 256>>>(dict);
    k_gram<<<NA, 128>>>();
    dim3 g(NA / 128, MS / 128);
    k_gemm<<<g, 256>>>(ze);
    k_omp<<<MS / SIG, 128>>>(out_sup, out_cf);
    k_recon<<<MS / 32, 256>>>(ze, out_sup, out_cf, out_zdl);
    k_loss<<<1, 256>>>(out_loss);
}

// round 4
// speedup vs baseline: 2.5602x; 1.5520x over previous
#include <cuda_runtime.h>
#include <cuda_bf16.h>
#include <math.h>

#define CM 64
#define NA 512
#define MS 32768
#define KS 5
#define HW 4096
#define CHW 262144
#define NUMEL 2097152.0f
#define FULL 0xffffffffu

__device__ float g_DnT[NA * CM];
__device__ float g_Dn[CM * NA];
__device__ float g_G[NA * NA];
__device__ float g_H[(size_t)MS * NA];
__device__ float g_partial[8192];

// ---------------------------------------------------------------------------
// Kernel 1: normalize dictionary columns, write both layouts
// ---------------------------------------------------------------------------
__global__ void k_norm(const float* __restrict__ dict) {
    int n = blockIdx.x * blockDim.x + threadIdx.x;
    if (n >= NA) return;
    float s = 0.f;
    #pragma unroll
    for (int c = 0; c < CM; c++) {
        float v = dict[c * NA + n];
        s += v * v;
    }
    float inv = 1.f / fmaxf(sqrtf(s), 1e-10f);
    #pragma unroll
    for (int c = 0; c < CM; c++) {
        float v = dict[c * NA + n] * inv;
        g_DnT[n * CM + c] = v;
        g_Dn[c * NA + n] = v;
    }
}

// ---------------------------------------------------------------------------
// Kernel 2: Gram matrix G = Dn^T Dn
// ---------------------------------------------------------------------------
__global__ void k_gram() {
    __shared__ float di[CM];
    int i = blockIdx.x;
    if (threadIdx.x < CM / 4)
        ((float4*)di)[threadIdx.x] = ((const float4*)(g_DnT + i * CM))[threadIdx.x];
    __syncthreads();
    for (int j = threadIdx.x; j < NA; j += blockDim.x) {
        const float4* dj = (const float4*)(g_DnT + j * CM);
        float s = 0.f;
        #pragma unroll
        for (int c = 0; c < CM / 4; c++) {
            float4 v = dj[c];
            s += di[c * 4 + 0] * v.x + di[c * 4 + 1] * v.y
               + di[c * 4 + 2] * v.z + di[c * 4 + 3] * v.w;
        }
        g_G[(size_t)i * NA + j] = s;
    }
}

// ---------------------------------------------------------------------------
// Kernel 3: H = X^T Dn. 128x128x8 tiles, 8x8 register blocking.
// ---------------------------------------------------------------------------
__global__ __launch_bounds__(256, 2) void k_gemm(const float* __restrict__ ze) {
    __shared__ float As[8][128];
    __shared__ float Bs[8][128];
    int tx = threadIdx.x & 15, ty = threadIdx.x >> 4;
    int m0 = blockIdx.y * 128, n0 = blockIdx.x * 128;
    int bb = m0 >> 12;
    int p0 = m0 & (HW - 1);
    const float* zb = ze + (size_t)bb * CHW + p0;

    float acc[8][8];
    #pragma unroll
    for (int i = 0; i < 8; i++)
        #pragma unroll
        for (int j = 0; j < 8; j++) acc[i][j] = 0.f;

    int lidx = threadIdx.x * 4;
    int lk = lidx >> 7;
    int lm = lidx & 127;

    for (int kk = 0; kk < CM; kk += 8) {
        float4 av = *(const float4*)(zb + (size_t)(kk + lk) * HW + lm);
        float4 bv = *(const float4*)(g_Dn + (size_t)(kk + lk) * NA + n0 + lm);
        *(float4*)&As[lk][lm] = av;
        *(float4*)&Bs[lk][lm] = bv;
        __syncthreads();
        #pragma unroll
        for (int k = 0; k < 8; k++) {
            float4 a0 = *(float4*)&As[k][ty * 8];
            float4 a1 = *(float4*)&As[k][ty * 8 + 4];
            float4 b0 = *(float4*)&Bs[k][tx * 8];
            float4 b1 = *(float4*)&Bs[k][tx * 8 + 4];
            float ar[8] = {a0.x, a0.y, a0.z, a0.w, a1.x, a1.y, a1.z, a1.w};
            float br[8] = {b0.x, b0.y, b0.z, b0.w, b1.x, b1.y, b1.z, b1.w};
            #pragma unroll
            for (int i = 0; i < 8; i++)
                #pragma unroll
                for (int j = 0; j < 8; j++)
                    acc[i][j] = fmaf(ar[i], br[j], acc[i][j]);
        }
        __syncthreads();
    }
    #pragma unroll
    for (int i = 0; i < 8; i++) {
        int m = m0 + ty * 8 + i;
        float* o = &g_H[(size_t)m * NA + n0 + tx * 8];
        *(float4*)o       = make_float4(acc[i][0], acc[i][1], acc[i][2], acc[i][3]);
        *(float4*)(o + 4) = make_float4(acc[i][4], acc[i][5], acc[i][6], acc[i][7]);
    }
}

// ---------------------------------------------------------------------------
// Kernel 4: OMP — fully register-resident, one warp per signal, zero smem.
// h and the 4 cached G rows live in registers. Argmax fused into updates.
// The tiny Cholesky runs redundantly on all lanes (inputs are warp-uniform).
// ---------------------------------------------------------------------------
__global__ __launch_bounds__(128) void k_omp(float* __restrict__ out_sup,
                                             float* __restrict__ out_cf) {
    const int lane = threadIdx.x & 31;
    const int m = (blockIdx.x * 128 + threadIdx.x) >> 5;
    const float4* Hb4 = (const float4*)(g_H + (size_t)m * NA);

    float4 h[4];          // this lane's 16 h values (indices 4*(lane+32j)+c)
    float4 R[4][4];       // cached G rows for selected atoms 0..3
    float  L[15];         // lower-triangular Cholesky (packed)
    float  gam[5], hs[5];
    int    sel[5];

    // load h_bar + initial max tracking
    float bv = -1.f, sv = 0.f;
    int bi = 0;
#pragma unroll
    for (int j = 0; j < 4; j++) {
        float4 v4 = __ldg(&Hb4[lane + 32 * j]);
        h[j] = v4;
        int base = 4 * (lane + 32 * j);
        float v;
        v = fabsf(v4.x); if (v > bv) { bv = v; sv = v4.x; bi = base;     }
        v = fabsf(v4.y); if (v > bv) { bv = v; sv = v4.y; bi = base + 1; }
        v = fabsf(v4.z); if (v > bv) { bv = v; sv = v4.z; bi = base + 2; }
        v = fabsf(v4.w); if (v > bv) { bv = v; sv = v4.w; bi = base + 3; }
    }

#pragma unroll
    for (int k = 1; k <= KS; k++) {
        // ---- warp argmax reduce (value, signed value, index; lowest idx ties)
#pragma unroll
        for (int off = 16; off; off >>= 1) {
            float ov = __shfl_down_sync(FULL, bv, off);
            float os = __shfl_down_sync(FULL, sv, off);
            int   oi = __shfl_down_sync(FULL, bi, off);
            if (ov > bv || (ov == bv && oi < bi)) { bv = ov; sv = os; bi = oi; }
        }
        bi = __shfl_sync(FULL, bi, 0);
        sv = __shfl_sync(FULL, sv, 0);

        const float* Grow = g_G + (size_t)bi * NA;

        // ---- uniform broadcast loads: Gv[t] = G[bi][sel_t] (L2-hot)
        float Gv[4];
#pragma unroll
        for (int t = 0; t < 4; t++)
            if (t < k - 1) Gv[t] = __ldg(Grow + sel[t]);

        // reconstruct h_bar[bi] = h_cur[bi] + sum_t gam_prev[t]*G[bi][sel_t]
        float hbv = sv;
#pragma unroll
        for (int t = 0; t < 4; t++)
            if (t < k - 1) hbv = fmaf(gam[t], Gv[t], hbv);

        // ---- Cholesky rank-1 extension (all lanes, uniform)
        if (k > 1) {
            float w[4], ww = 0.f;
#pragma unroll
            for (int i = 0; i < 4; i++) {
                if (i < k - 1) {
                    float a = Gv[i];
#pragma unroll
                    for (int j = 0; j < 4; j++)
                        if (j < i) a -= L[i * (i + 1) / 2 + j] * w[j];
                    w[i] = a / L[i * (i + 1) / 2 + i];
                    ww += w[i] * w[i];
                }
            }
            const int r = k - 1;
#pragma unroll
            for (int j = 0; j < 4; j++)
                if (j < r) L[r * (r + 1) / 2 + j] = w[j];
            L[r * (r + 1) / 2 + r] = sqrtf(fmaxf(1.f - ww, 1e-12f));
        } else {
            L[0] = 1.f;
        }
        sel[k - 1] = bi;
        hs[k - 1] = hbv;

        // ---- cho_solve (k x k, uniform)
        float y[5], g2[5];
#pragma unroll
        for (int i = 0; i < 5; i++) {
            if (i < k) {
                float a = hs[i];
#pragma unroll
                for (int j = 0; j < 5; j++)
                    if (j < i) a -= L[i * (i + 1) / 2 + j] * y[j];
                y[i] = a / L[i * (i + 1) / 2 + i];
            }
        }
#pragma unroll
        for (int i = 4; i >= 0; i--) {
            if (i < k) {
                float a = y[i];
#pragma unroll
                for (int j = 0; j < 5; j++)
                    if (j > i && j < k) a -= L[j * (j + 1) / 2 + i] * g2[j];
                g2[i] = a / L[i * (i + 1) / 2 + i];
            }
        }
        float dg[5];
#pragma unroll
        for (int i = 0; i < 5; i++) {
            if (i < k) {
                float old = (i < k - 1) ? gam[i] : 0.f;
                dg[i] = g2[i] - old;
                gam[i] = g2[i];
            }
        }

        // ---- fused h update + next-argmax tracking (pure registers + L2 row)
        if (k < KS) {
            const float4* Gr4 = (const float4*)Grow;
            bv = -1.f;
#pragma unroll
            for (int j = 0; j < 4; j++) {
                float4 gv = __ldg(&Gr4[lane + 32 * j]);
                R[k - 1][j] = gv;
                float4 a;
                a.x = dg[k - 1] * gv.x; a.y = dg[k - 1] * gv.y;
                a.z = dg[k - 1] * gv.z; a.w = dg[k - 1] * gv.w;
#pragma unroll
                for (int t = 0; t < 4; t++) {
                    if (t < k - 1) {
                        float4 rv = R[t][j];
                        a.x = fmaf(dg[t], rv.x, a.x);
                        a.y = fmaf(dg[t], rv.y, a.y);
                        a.z = fmaf(dg[t], rv.z, a.z);
                        a.w = fmaf(dg[t], rv.w, a.w);
                    }
                }
                float4 hv = h[j];
                hv.x -= a.x; hv.y -= a.y; hv.z -= a.z; hv.w -= a.w;
                h[j] = hv;
                int base = 4 * (lane + 32 * j);
                float v;
                v = fabsf(hv.x); if (v > bv) { bv = v; sv = hv.x; bi = base;     }
                v = fabsf(hv.y); if (v > bv) { bv = v; sv = hv.y; bi = base + 1; }
                v = fabsf(hv.z); if (v > bv) { bv = v; sv = hv.z; bi = base + 2; }
                v = fabsf(hv.w); if (v > bv) { bv = v; sv = hv.w; bi = base + 3; }
            }
        }
    }

    // ---- outputs (constant-index select chains; values are warp-uniform)
    if (lane < KS) {
        float s = (lane == 0) ? (float)sel[0] :
                  (lane == 1) ? (float)sel[1] :
                  (lane == 2) ? (float)sel[2] :
                  (lane == 3) ? (float)sel[3] : (float)sel[4];
        float c = (lane == 0) ? gam[0] :
                  (lane == 1) ? gam[1] :
                  (lane == 2) ? gam[2] :
                  (lane == 3) ? gam[3] : gam[4];
        out_sup[(size_t)m * KS + lane] = s;
        out_cf[(size_t)m * KS + lane]  = c;
    }
}

// ---------------------------------------------------------------------------
// Kernel 5: coalesced reconstruction + squared error
// ---------------------------------------------------------------------------
__global__ __launch_bounds__(256) void k_recon(const float* __restrict__ ze,
                                               const float* __restrict__ sup,
                                               const float* __restrict__ cf,
                                               float* __restrict__ out_zdl) {
    __shared__ float tile[CM][33];
    __shared__ float red[256];

    int m0 = blockIdx.x * 32;
    int b  = m0 >> 12;
    int p0 = m0 & (HW - 1);
    int wid = threadIdx.x >> 5, lane = threadIdx.x & 31;

    for (int s = wid; s < 32; s += 8) {
        int m = m0 + s;
        int   si[KS];
        float ci[KS];
        #pragma unroll
        for (int t = 0; t < KS; t++) {
            si[t] = (int)sup[(size_t)m * KS + t];
            ci[t] = cf[(size_t)m * KS + t];
        }
        #pragma unroll
        for (int half = 0; half < 2; half++) {
            int c = lane + 32 * half;
            float r = 0.f;
            #pragma unroll
            for (int t = 0; t < KS; t++)
                r = fmaf(ci[t], g_DnT[si[t] * CM + c], r);
            tile[c][s] = r;
        }
    }
    __syncthreads();

    int p  = threadIdx.x & 31;
    int cb = threadIdx.x >> 5;
    float err = 0.f;
    #pragma unroll
    for (int j = 0; j < 8; j++) {
        int c = cb * 8 + j;
        size_t zi = (size_t)b * CHW + (size_t)c * HW + p0 + p;
        float r = tile[c][p];
        float x = ze[zi];
        float d = r - x;
        err += d * d;
        out_zdl[zi] = r;
    }
    red[threadIdx.x] = err;
    __syncthreads();
    for (int o = 128; o; o >>= 1) {
        if (threadIdx.x < o) red[threadIdx.x] += red[threadIdx.x + o];
        __syncthreads();
    }
    if (threadIdx.x == 0) g_partial[blockIdx.x] = red[0];
}

// ---------------------------------------------------------------------------
// Kernel 6: deterministic loss reduction. loss = 1.25 * MSE
// ---------------------------------------------------------------------------
__global__ void k_loss(float* __restrict__ out_loss) {
    __shared__ float red[256];
    float s = 0.f;
    for (int i = threadIdx.x; i < 1024; i += 256) s += g_partial[i];
    red[threadIdx.x] = s;
    __syncthreads();
    for (int o = 128; o; o >>= 1) {
        if (threadIdx.x < o) red[threadIdx.x] += red[threadIdx.x + o];
        __syncthreads();
    }
    if (threadIdx.x == 0) out_loss[0] = 1.25f * red[0] / NUMEL;
}

// ---------------------------------------------------------------------------
extern "C" void kernel_launch(void* const* d_in, const int* in_sizes, int n_in,
                              void* d_out, int out_size) {
    const float* ze   = (const float*)d_in[0];
    const float* dict = (const float*)d_in[1];
    float* out = (float*)d_out;
    float* out_zdl  = out;
    float* out_loss = out + 2097152;
    float* out_sup  = out + 2097153;
    float* out_cf   = out + 2097153 + 163840;

    k_norm<<<2, 256>>>(dict);
    k_gram<<<NA, 128>>>();
    dim3 g(NA / 128, MS / 128);
    k_gemm<<<g, 256>>>(ze);
    k_omp<<<MS / 4, 128>>>(out_sup, out_cf);
    k_recon<<<MS / 32, 256>>>(ze, out_sup, out_cf, out_zdl);
    k_loss<<<1, 256>>>(out_loss);
}

// round 5
// speedup vs baseline: 3.1037x; 1.2123x over previous
#include <cuda_runtime.h>
#include <cuda_bf16.h>
#include <math.h>

#define CM 64
#define NA 512
#define MS 32768
#define KS 5
#define HW 4096
#define CHW 262144
#define NUMEL 2097152.0f
#define FULL 0xffffffffu

__device__ float g_DnT[NA * CM];
__device__ float g_Dn[CM * NA];
__device__ float g_G[NA * NA];
__device__ float g_H[(size_t)MS * NA];
__device__ float g_partial[8192];

// ---------------------------------------------------------------------------
// Kernel 1: normalize dictionary columns, write both layouts
// ---------------------------------------------------------------------------
__global__ void k_norm(const float* __restrict__ dict) {
    int n = blockIdx.x * blockDim.x + threadIdx.x;
    if (n >= NA) return;
    float s = 0.f;
    #pragma unroll
    for (int c = 0; c < CM; c++) {
        float v = dict[c * NA + n];
        s += v * v;
    }
    float inv = 1.f / fmaxf(sqrtf(s), 1e-10f);
    #pragma unroll
    for (int c = 0; c < CM; c++) {
        float v = dict[c * NA + n] * inv;
        g_DnT[n * CM + c] = v;
        g_Dn[c * NA + n] = v;
    }
}

// ---------------------------------------------------------------------------
// Kernel 2: Gram matrix G = Dn^T Dn
// ---------------------------------------------------------------------------
__global__ void k_gram() {
    __shared__ float di[CM];
    int i = blockIdx.x;
    if (threadIdx.x < CM / 4)
        ((float4*)di)[threadIdx.x] = ((const float4*)(g_DnT + i * CM))[threadIdx.x];
    __syncthreads();
    for (int j = threadIdx.x; j < NA; j += blockDim.x) {
        const float4* dj = (const float4*)(g_DnT + j * CM);
        float s = 0.f;
        #pragma unroll
        for (int c = 0; c < CM / 4; c++) {
            float4 v = dj[c];
            s += di[c * 4 + 0] * v.x + di[c * 4 + 1] * v.y
               + di[c * 4 + 2] * v.z + di[c * 4 + 3] * v.w;
        }
        g_G[(size_t)i * NA + j] = s;
    }
}

// ---------------------------------------------------------------------------
// Kernel 3: H = X^T Dn. 128x128 tiles, K-tile=32, 8x8 register blocking.
// ---------------------------------------------------------------------------
__global__ __launch_bounds__(256, 2) void k_gemm(const float* __restrict__ ze) {
    __shared__ float As[32][128];
    __shared__ float Bs[32][128];
    int tx = threadIdx.x & 15, ty = threadIdx.x >> 4;
    int m0 = blockIdx.y * 128, n0 = blockIdx.x * 128;
    int bb = m0 >> 12;
    int p0 = m0 & (HW - 1);
    const float* zb = ze + (size_t)bb * CHW + p0;

    float acc[8][8];
    #pragma unroll
    for (int i = 0; i < 8; i++)
        #pragma unroll
        for (int j = 0; j < 8; j++) acc[i][j] = 0.f;

    #pragma unroll
    for (int kk0 = 0; kk0 < CM; kk0 += 32) {
        // load 32x128 tiles: 1024 float4 per array, 4 per thread
        #pragma unroll
        for (int r = 0; r < 4; r++) {
            int idx = r * 256 + threadIdx.x;
            int kk = idx >> 5, m4 = (idx & 31) << 2;
            *(float4*)&As[kk][m4] = *(const float4*)(zb + (size_t)(kk0 + kk) * HW + m4);
            *(float4*)&Bs[kk][m4] = *(const float4*)(g_Dn + (size_t)(kk0 + kk) * NA + n0 + m4);
        }
        __syncthreads();
        #pragma unroll
        for (int k = 0; k < 32; k++) {
            float4 a0 = *(float4*)&As[k][ty * 8];
            float4 a1 = *(float4*)&As[k][ty * 8 + 4];
            float4 b0 = *(float4*)&Bs[k][tx * 8];
            float4 b1 = *(float4*)&Bs[k][tx * 8 + 4];
            float ar[8] = {a0.x, a0.y, a0.z, a0.w, a1.x, a1.y, a1.z, a1.w};
            float br[8] = {b0.x, b0.y, b0.z, b0.w, b1.x, b1.y, b1.z, b1.w};
            #pragma unroll
            for (int i = 0; i < 8; i++)
                #pragma unroll
                for (int j = 0; j < 8; j++)
                    acc[i][j] = fmaf(ar[i], br[j], acc[i][j]);
        }
        __syncthreads();
    }
    #pragma unroll
    for (int i = 0; i < 8; i++) {
        int m = m0 + ty * 8 + i;
        float* o = &g_H[(size_t)m * NA + n0 + tx * 8];
        *(float4*)o       = make_float4(acc[i][0], acc[i][1], acc[i][2], acc[i][3]);
        *(float4*)(o + 4) = make_float4(acc[i][4], acc[i][5], acc[i][6], acc[i][7]);
    }
}

// ---------------------------------------------------------------------------
// Kernel 4: OMP — register-resident, one warp per signal, zero smem.
// Divide-free solver (reciprocal diagonals), incremental forward solve,
// REDUX-based argmax, 3 cached G rows (the 4th is never re-read).
// ---------------------------------------------------------------------------
__global__ __launch_bounds__(128, 5) void k_omp(float* __restrict__ out_sup,
                                                float* __restrict__ out_cf) {
    const int lane = threadIdx.x & 31;
    const int m = (blockIdx.x * 128 + threadIdx.x) >> 5;
    const float4* Hb4 = (const float4*)(g_H + (size_t)m * NA);

    float4 h[4];          // this lane's 16 h values (index 4*(lane+32j)+c)
    float4 R[3][4];       // cached G rows for selected atoms 0..2
    float  Lo[10];        // off-diagonal L rows 1..4 (packed (i-1)i/2+j)
    float  Linv[5];       // reciprocal diagonals
    float  y[5];          // forward-solve prefix (stable across iterations)
    float  gam[5];
    int    sel[5];

    // load h_bar + initial max tracking
    float bv = -1.f, sv = 0.f;
    int bi = 0;
#pragma unroll
    for (int j = 0; j < 4; j++) {
        float4 v4 = __ldg(&Hb4[lane + 32 * j]);
        h[j] = v4;
        int base = 4 * (lane + 32 * j);
        float v;
        v = fabsf(v4.x); if (v > bv) { bv = v; sv = v4.x; bi = base;     }
        v = fabsf(v4.y); if (v > bv) { bv = v; sv = v4.y; bi = base + 1; }
        v = fabsf(v4.z); if (v > bv) { bv = v; sv = v4.z; bi = base + 2; }
        v = fabsf(v4.w); if (v > bv) { bv = v; sv = v4.w; bi = base + 3; }
    }

#pragma unroll
    for (int k = 1; k <= KS; k++) {
        // ---- warp argmax via REDUX (abs bits are order-preserving)
        unsigned mybits = __float_as_uint(bv);
        unsigned maxb = __reduce_max_sync(FULL, mybits);
        int cand = (mybits == maxb) ? bi : (1 << 30);
        bi = __reduce_min_sync(FULL, cand);
        unsigned own = __ballot_sync(FULL, cand == bi);
        sv = __shfl_sync(FULL, sv, __ffs(own) - 1);

        const float* Grow = g_G + (size_t)bi * NA;

        // ---- uniform broadcast loads: Gv[t] = G[bi][sel_t] (L2-hot)
        float Gv[4];
#pragma unroll
        for (int t = 0; t < 4; t++)
            if (t < k - 1) Gv[t] = __ldg(Grow + sel[t]);

        // reconstruct h_bar[bi] = h_cur[bi] + sum_t gam[t]*G[bi][sel_t]
        float hbv = sv;
#pragma unroll
        for (int t = 0; t < 4; t++)
            if (t < k - 1) hbv = fmaf(gam[t], Gv[t], hbv);

        // ---- Cholesky rank-1 extension (divide-free, all lanes uniform)
        if (k > 1) {
            float w[4], ww = 0.f;
#pragma unroll
            for (int i = 0; i < 4; i++) {
                if (i < k - 1) {
                    float a = Gv[i];
#pragma unroll
                    for (int j = 0; j < 4; j++)
                        if (j < i) a -= Lo[(i - 1) * i / 2 + j] * w[j];
                    if (i > 0) a *= Linv[i];   // row 0 diag == 1
                    w[i] = a;
                    ww += a * a;
                }
            }
            const int r = k - 1;
#pragma unroll
            for (int j = 0; j < 4; j++)
                if (j < r) Lo[(r - 1) * r / 2 + j] = w[j];
            Linv[r] = rsqrtf(fmaxf(1.f - ww, 1e-12f));
        } else {
            Linv[0] = 1.f;
        }
        sel[k - 1] = bi;

        // ---- incremental forward solve: only y[k-1] is new
        {
            const int i = k - 1;
            float a = hbv;
#pragma unroll
            for (int j = 0; j < 4; j++)
                if (j < i) a -= Lo[(i - 1) * i / 2 + j] * y[j];
            y[i] = a * Linv[i];
        }

        // ---- backward solve: L^T g2 = y
        float g2[5];
#pragma unroll
        for (int i = 4; i >= 0; i--) {
            if (i < k) {
                float a = y[i];
#pragma unroll
                for (int j = 0; j < 5; j++)
                    if (j > i && j < k) a -= Lo[(j - 1) * j / 2 + i] * g2[j];
                g2[i] = a * Linv[i];
            }
        }
        float dg[5];
#pragma unroll
        for (int i = 0; i < 5; i++) {
            if (i < k) {
                float old = (i < k - 1) ? gam[i] : 0.f;
                dg[i] = g2[i] - old;
                gam[i] = g2[i];
            }
        }

        // ---- fused h update + next-argmax tracking
        if (k < KS) {
            const float4* Gr4 = (const float4*)Grow;
            bv = -1.f;
#pragma unroll
            for (int j = 0; j < 4; j++) {
                float4 gv = __ldg(&Gr4[lane + 32 * j]);
                if (k - 1 < 3) R[k - 1 < 3 ? k - 1 : 0][j] = gv;
                float4 a;
                a.x = dg[k - 1] * gv.x; a.y = dg[k - 1] * gv.y;
                a.z = dg[k - 1] * gv.z; a.w = dg[k - 1] * gv.w;
#pragma unroll
                for (int t = 0; t < 3; t++) {
                    if (t < k - 1) {
                        float4 rv = R[t][j];
                        a.x = fmaf(dg[t], rv.x, a.x);
                        a.y = fmaf(dg[t], rv.y, a.y);
                        a.z = fmaf(dg[t], rv.z, a.z);
                        a.w = fmaf(dg[t], rv.w, a.w);
                    }
                }
                float4 hv = h[j];
                hv.x -= a.x; hv.y -= a.y; hv.z -= a.z; hv.w -= a.w;
                h[j] = hv;
                int base = 4 * (lane + 32 * j);
                float v;
                v = fabsf(hv.x); if (v > bv) { bv = v; sv = hv.x; bi = base;     }
                v = fabsf(hv.y); if (v > bv) { bv = v; sv = hv.y; bi = base + 1; }
                v = fabsf(hv.z); if (v > bv) { bv = v; sv = hv.z; bi = base + 2; }
                v = fabsf(hv.w); if (v > bv) { bv = v; sv = hv.w; bi = base + 3; }
            }
        }
    }

    // ---- outputs (constant-index select chains; values are warp-uniform)
    if (lane < KS) {
        float s = (lane == 0) ? (float)sel[0] :
                  (lane == 1) ? (float)sel[1] :
                  (lane == 2) ? (float)sel[2] :
                  (lane == 3) ? (float)sel[3] : (float)sel[4];
        float c = (lane == 0) ? gam[0] :
                  (lane == 1) ? gam[1] :
                  (lane == 2) ? gam[2] :
                  (lane == 3) ? gam[3] : gam[4];
        out_sup[(size_t)m * KS + lane] = s;
        out_cf[(size_t)m * KS + lane]  = c;
    }
}

// ---------------------------------------------------------------------------
// Kernel 5: coalesced reconstruction + squared error
// ---------------------------------------------------------------------------
__global__ __launch_bounds__(256) void k_recon(const float* __restrict__ ze,
                                               const float* __restrict__ sup,
                                               const float* __restrict__ cf,
                                               float* __restrict__ out_zdl) {
    __shared__ float tile[CM][33];
    __shared__ float red[256];

    int m0 = blockIdx.x * 32;
    int b  = m0 >> 12;
    int p0 = m0 & (HW - 1);
    int wid = threadIdx.x >> 5, lane = threadIdx.x & 31;

    for (int s = wid; s < 32; s += 8) {
        int m = m0 + s;
        int   si[KS];
        float ci[KS];
        #pragma unroll
        for (int t = 0; t < KS; t++) {
            si[t] = (int)sup[(size_t)m * KS + t];
            ci[t] = cf[(size_t)m * KS + t];
        }
        #pragma unroll
        for (int half = 0; half < 2; half++) {
            int c = lane + 32 * half;
            float r = 0.f;
            #pragma unroll
            for (int t = 0; t < KS; t++)
                r = fmaf(ci[t], g_DnT[si[t] * CM + c], r);
            tile[c][s] = r;
        }
    }
    __syncthreads();

    int p  = threadIdx.x & 31;
    int cb = threadIdx.x >> 5;
    float err = 0.f;
    #pragma unroll
    for (int j = 0; j < 8; j++) {
        int c = cb * 8 + j;
        size_t zi = (size_t)b * CHW + (size_t)c * HW + p0 + p;
        float r = tile[c][p];
        float x = ze[zi];
        float d = r - x;
        err += d * d;
        out_zdl[zi] = r;
    }
    red[threadIdx.x] = err;
    __syncthreads();
    for (int o = 128; o; o >>= 1) {
        if (threadIdx.x < o) red[threadIdx.x] += red[threadIdx.x + o];
        __syncthreads();
    }
    if (threadIdx.x == 0) g_partial[blockIdx.x] = red[0];
}

// ---------------------------------------------------------------------------
// Kernel 6: deterministic loss reduction. loss = 1.25 * MSE
// ---------------------------------------------------------------------------
__global__ void k_loss(float* __restrict__ out_loss) {
    __shared__ float red[256];
    float s = 0.f;
    for (int i = threadIdx.x; i < 1024; i += 256) s += g_partial[i];
    red[threadIdx.x] = s;
    __syncthreads();
    for (int o = 128; o; o >>= 1) {
        if (threadIdx.x < o) red[threadIdx.x] += red[threadIdx.x + o];
        __syncthreads();
    }
    if (threadIdx.x == 0) out_loss[0] = 1.25f * red[0] / NUMEL;
}

// ---------------------------------------------------------------------------
extern "C" void kernel_launch(void* const* d_in, const int* in_sizes, int n_in,
                              void* d_out, int out_size) {
    const float* ze   = (const float*)d_in[0];
    const float* dict = (const float*)d_in[1];
    float* out = (float*)d_out;
    float* out_zdl  = out;
    float* out_loss = out + 2097152;
    float* out_sup  = out + 2097153;
    float* out_cf   = out + 2097153 + 163840;

    k_norm<<<2, 256>>>(dict);
    k_gram<<<NA, 128>>>();
    dim3 g(NA / 128, MS / 128);
    k_gemm<<<g, 256>>>(ze);
    k_omp<<<MS / 4, 128>>>(out_sup, out_cf);
    k_recon<<<MS / 32, 256>>>(ze, out_sup, out_cf, out_zdl);
    k_loss<<<1, 256>>>(out_loss);
}

// round 6
// speedup vs baseline: 3.2257x; 1.0393x over previous
#include <cuda_runtime.h>
#include <cuda_bf16.h>
#include <math.h>

#define CM 64
#define NA 512
#define MS 32768
#define KS 5
#define HW 4096
#define CHW 262144
#define NUMEL 2097152.0f
#define FULL 0xffffffffu

typedef unsigned long long u64;

// packed fp32x2 helpers (sm_103a; ptxas never emits these on its own)
#define F32X2_FMA(d, a, b) \
    asm("fma.rn.f32x2 %0, %1, %2, %0;" : "+l"(d) : "l"(a), "l"(b))
#define F32X2_MUL(d, a, b) \
    asm("mul.rn.f32x2 %0, %1, %2;" : "=l"(d) : "l"(a), "l"(b))
#define F32X2_ADD(d, a, b) \
    asm("add.rn.f32x2 %0, %1, %2;" : "=l"(d) : "l"(a), "l"(b))
#define F32X2_DUP(d, x) \
    asm("mov.b64 %0, {%1, %1};" : "=l"(d) : "r"(__float_as_uint(x)))

__device__ __forceinline__ float u64_lo(u64 v) { return __uint_as_float((unsigned)v); }
__device__ __forceinline__ float u64_hi(u64 v) { return __uint_as_float((unsigned)(v >> 32)); }

__device__ float g_DnT[NA * CM];
__device__ float g_Dn[CM * NA];
__device__ float g_G[NA * NA];
__device__ float g_H[(size_t)MS * NA];
__device__ float g_partial[8192];

// ---------------------------------------------------------------------------
// Kernel 1: normalize dictionary columns, write both layouts
// ---------------------------------------------------------------------------
__global__ void k_norm(const float* __restrict__ dict) {
    int n = blockIdx.x * blockDim.x + threadIdx.x;
    if (n >= NA) return;
    float s = 0.f;
    #pragma unroll
    for (int c = 0; c < CM; c++) {
        float v = dict[c * NA + n];
        s += v * v;
    }
    float inv = 1.f / fmaxf(sqrtf(s), 1e-10f);
    #pragma unroll
    for (int c = 0; c < CM; c++) {
        float v = dict[c * NA + n] * inv;
        g_DnT[n * CM + c] = v;
        g_Dn[c * NA + n] = v;
    }
}

// ---------------------------------------------------------------------------
// Kernel 2: Gram matrix G = Dn^T Dn
// ---------------------------------------------------------------------------
__global__ void k_gram() {
    __shared__ float di[CM];
    int i = blockIdx.x;
    if (threadIdx.x < CM / 4)
        ((float4*)di)[threadIdx.x] = ((const float4*)(g_DnT + i * CM))[threadIdx.x];
    __syncthreads();
    for (int j = threadIdx.x; j < NA; j += blockDim.x) {
        const float4* dj = (const float4*)(g_DnT + j * CM);
        float s = 0.f;
        #pragma unroll
        for (int c = 0; c < CM / 4; c++) {
            float4 v = dj[c];
            s += di[c * 4 + 0] * v.x + di[c * 4 + 1] * v.y
               + di[c * 4 + 2] * v.z + di[c * 4 + 3] * v.w;
        }
        g_G[(size_t)i * NA + j] = s;
    }
}

// ---------------------------------------------------------------------------
// Kernel 3: H = X^T Dn. 128x128 tiles, K-tile=32, 8x8 blocking via FFMA2.
// Accumulators are fp32x2 pairs over the j (N) dimension.
// ---------------------------------------------------------------------------
__global__ __launch_bounds__(256, 2) void k_gemm(const float* __restrict__ ze) {
    __shared__ float As[32][128];
    __shared__ float Bs[32][128];
    int tx = threadIdx.x & 15, ty = threadIdx.x >> 4;
    int m0 = blockIdx.y * 128, n0 = blockIdx.x * 128;
    int bb = m0 >> 12;
    int p0 = m0 & (HW - 1);
    const float* zb = ze + (size_t)bb * CHW + p0;

    u64 acc2[8][4];
    #pragma unroll
    for (int i = 0; i < 8; i++)
        #pragma unroll
        for (int j = 0; j < 4; j++) acc2[i][j] = 0ull;

    #pragma unroll
    for (int kk0 = 0; kk0 < CM; kk0 += 32) {
        #pragma unroll
        for (int r = 0; r < 4; r++) {
            int idx = r * 256 + threadIdx.x;
            int kk = idx >> 5, m4 = (idx & 31) << 2;
            *(float4*)&As[kk][m4] = *(const float4*)(zb + (size_t)(kk0 + kk) * HW + m4);
            *(float4*)&Bs[kk][m4] = *(const float4*)(g_Dn + (size_t)(kk0 + kk) * NA + n0 + m4);
        }
        __syncthreads();
        #pragma unroll
        for (int k = 0; k < 32; k++) {
            float4 a0 = *(float4*)&As[k][ty * 8];
            float4 a1 = *(float4*)&As[k][ty * 8 + 4];
            ulonglong2 bp0 = *(ulonglong2*)&Bs[k][tx * 8];
            ulonglong2 bp1 = *(ulonglong2*)&Bs[k][tx * 8 + 4];
            float ar[8] = {a0.x, a0.y, a0.z, a0.w, a1.x, a1.y, a1.z, a1.w};
            u64 bp[4] = {bp0.x, bp0.y, bp1.x, bp1.y};
            #pragma unroll
            for (int i = 0; i < 8; i++) {
                u64 ad;
                F32X2_DUP(ad, ar[i]);
                #pragma unroll
                for (int j = 0; j < 4; j++)
                    F32X2_FMA(acc2[i][j], ad, bp[j]);
            }
        }
        __syncthreads();
    }
    #pragma unroll
    for (int i = 0; i < 8; i++) {
        int m = m0 + ty * 8 + i;
        u64* o = (u64*)&g_H[(size_t)m * NA + n0 + tx * 8];
        ulonglong2 s0, s1;
        s0.x = acc2[i][0]; s0.y = acc2[i][1];
        s1.x = acc2[i][2]; s1.y = acc2[i][3];
        *(ulonglong2*)o       = s0;
        *(ulonglong2*)(o + 2) = s1;
    }
}

// ---------------------------------------------------------------------------
// Kernel 4: OMP — register-resident, one warp per signal, zero smem.
// h / G rows / R cache live as fp32x2 pairs; update sweep uses FFMA2 with
// negated deltas (bitwise identical to h -= sum dg*G). Divide-free solver.
// ---------------------------------------------------------------------------
__global__ __launch_bounds__(128, 5) void k_omp(float* __restrict__ out_sup,
                                                float* __restrict__ out_cf) {
    const int lane = threadIdx.x & 31;
    const int m = (blockIdx.x * 128 + threadIdx.x) >> 5;
    const ulonglong2* Hb2 = (const ulonglong2*)(g_H + (size_t)m * NA);

    u64   h2[8];          // 16 h values as 8 pairs; pair 2j+q covers elems 4*(lane+32j)+2q+{0,1}
    u64   R2[3][8];       // cached G rows for selected atoms 0..2
    float Lo[10];         // off-diagonal L rows 1..4 (packed (i-1)i/2+j)
    float Linv[5];        // reciprocal diagonals
    float y[5];
    float gam[5];
    int   sel[5];

    // load h_bar + initial max tracking
    float bv = -1.f, sv = 0.f;
    int bi = 0;
#pragma unroll
    for (int j = 0; j < 4; j++) {
        ulonglong2 v = __ldg(&Hb2[lane + 32 * j]);
        h2[2 * j] = v.x;
        h2[2 * j + 1] = v.y;
        int base = 4 * (lane + 32 * j);
        float e0 = u64_lo(v.x), e1 = u64_hi(v.x), e2 = u64_lo(v.y), e3 = u64_hi(v.y);
        float a;
        a = fabsf(e0); if (a > bv) { bv = a; sv = e0; bi = base;     }
        a = fabsf(e1); if (a > bv) { bv = a; sv = e1; bi = base + 1; }
        a = fabsf(e2); if (a > bv) { bv = a; sv = e2; bi = base + 2; }
        a = fabsf(e3); if (a > bv) { bv = a; sv = e3; bi = base + 3; }
    }

#pragma unroll
    for (int k = 1; k <= KS; k++) {
        // ---- warp argmax via REDUX (abs bits are order-preserving)
        unsigned mybits = __float_as_uint(bv);
        unsigned maxb = __reduce_max_sync(FULL, mybits);
        int cand = (mybits == maxb) ? bi : (1 << 30);
        bi = __reduce_min_sync(FULL, cand);
        unsigned own = __ballot_sync(FULL, cand == bi);
        sv = __shfl_sync(FULL, sv, __ffs(own) - 1);

        const float* Grow = g_G + (size_t)bi * NA;

        // ---- uniform broadcast loads: Gv[t] = G[bi][sel_t] (L2-hot)
        float Gv[4];
#pragma unroll
        for (int t = 0; t < 4; t++)
            if (t < k - 1) Gv[t] = __ldg(Grow + sel[t]);

        // reconstruct h_bar[bi] = h_cur[bi] + sum_t gam[t]*G[bi][sel_t]
        float hbv = sv;
#pragma unroll
        for (int t = 0; t < 4; t++)
            if (t < k - 1) hbv = fmaf(gam[t], Gv[t], hbv);

        // ---- Cholesky rank-1 extension (divide-free, all lanes uniform)
        if (k > 1) {
            float w[4], ww = 0.f;
#pragma unroll
            for (int i = 0; i < 4; i++) {
                if (i < k - 1) {
                    float a = Gv[i];
#pragma unroll
                    for (int j = 0; j < 4; j++)
                        if (j < i) a -= Lo[(i - 1) * i / 2 + j] * w[j];
                    if (i > 0) a *= Linv[i];
                    w[i] = a;
                    ww += a * a;
                }
            }
            const int r = k - 1;
#pragma unroll
            for (int j = 0; j < 4; j++)
                if (j < r) Lo[(r - 1) * r / 2 + j] = w[j];
            Linv[r] = rsqrtf(fmaxf(1.f - ww, 1e-12f));
        } else {
            Linv[0] = 1.f;
        }
        sel[k - 1] = bi;

        // ---- incremental forward solve: only y[k-1] is new
        {
            const int i = k - 1;
            float a = hbv;
#pragma unroll
            for (int j = 0; j < 4; j++)
                if (j < i) a -= Lo[(i - 1) * i / 2 + j] * y[j];
            y[i] = a * Linv[i];
        }

        // ---- backward solve: L^T g2 = y
        float g2[5];
#pragma unroll
        for (int i = 4; i >= 0; i--) {
            if (i < k) {
                float a = y[i];
#pragma unroll
                for (int j = 0; j < 5; j++)
                    if (j > i && j < k) a -= Lo[(j - 1) * j / 2 + i] * g2[j];
                g2[i] = a * Linv[i];
            }
        }
        float dg[5];
#pragma unroll
        for (int i = 0; i < 5; i++) {
            if (i < k) {
                float old = (i < k - 1) ? gam[i] : 0.f;
                dg[i] = g2[i] - old;
                gam[i] = g2[i];
            }
        }

        // ---- fused packed h update + next-argmax tracking
        if (k < KS) {
            const ulonglong2* Gr2 = (const ulonglong2*)Grow;
            u64 ndp[4];
#pragma unroll
            for (int t = 0; t < 4; t++)
                if (t < k) F32X2_DUP(ndp[t], -dg[t]);
            bv = -1.f;
#pragma unroll
            for (int j = 0; j < 4; j++) {
                ulonglong2 gv = __ldg(&Gr2[lane + 32 * j]);
                int base = 4 * (lane + 32 * j);
#pragma unroll
                for (int q = 0; q < 2; q++) {
                    u64 gp = q ? gv.y : gv.x;
                    int p = 2 * j + q;
                    if (k - 1 < 3) R2[k - 1 < 3 ? k - 1 : 0][p] = gp;
                    u64 a;
                    F32X2_MUL(a, ndp[k - 1], gp);
#pragma unroll
                    for (int t = 0; t < 3; t++)
                        if (t < k - 1) F32X2_FMA(a, ndp[t], R2[t][p]);
                    u64 hn;
                    F32X2_ADD(hn, h2[p], a);
                    h2[p] = hn;
                    float e0 = u64_lo(hn), e1 = u64_hi(hn);
                    float v;
                    v = fabsf(e0); if (v > bv) { bv = v; sv = e0; bi = base + 2 * q;     }
                    v = fabsf(e1); if (v > bv) { bv = v; sv = e1; bi = base + 2 * q + 1; }
                }
            }
        }
    }

    // ---- outputs (values are warp-uniform)
    if (lane < KS) {
        float s = (lane == 0) ? (float)sel[0] :
                  (lane == 1) ? (float)sel[1] :
                  (lane == 2) ? (float)sel[2] :
                  (lane == 3) ? (float)sel[3] : (float)sel[4];
        float c = (lane == 0) ? gam[0] :
                  (lane == 1) ? gam[1] :
                  (lane == 2) ? gam[2] :
                  (lane == 3) ? gam[3] : gam[4];
        out_sup[(size_t)m * KS + lane] = s;
        out_cf[(size_t)m * KS + lane]  = c;
    }
}

// ---------------------------------------------------------------------------
// Kernel 5: coalesced reconstruction + squared error
// ---------------------------------------------------------------------------
__global__ __launch_bounds__(256) void k_recon(const float* __restrict__ ze,
                                               const float* __restrict__ sup,
                                               const float* __restrict__ cf,
                                               float* __restrict__ out_zdl) {
    __shared__ float tile[CM][33];
    __shared__ float red[256];

    int m0 = blockIdx.x * 32;
    int b  = m0 >> 12;
    int p0 = m0 & (HW - 1);
    int wid = threadIdx.x >> 5, lane = threadIdx.x & 31;

    for (int s = wid; s < 32; s += 8) {
        int m = m0 + s;
        int   si[KS];
        float ci[KS];
        #pragma unroll
        for (int t = 0; t < KS; t++) {
            si[t] = (int)sup[(size_t)m * KS + t];
            ci[t] = cf[(size_t)m * KS + t];
        }
        #pragma unroll
        for (int half = 0; half < 2; half++) {
            int c = lane + 32 * half;
            float r = 0.f;
            #pragma unroll
            for (int t = 0; t < KS; t++)
                r = fmaf(ci[t], g_DnT[si[t] * CM + c], r);
            tile[c][s] = r;
        }
    }
    __syncthreads();

    int p  = threadIdx.x & 31;
    int cb = threadIdx.x >> 5;
    float err = 0.f;
    #pragma unroll
    for (int j = 0; j < 8; j++) {
        int c = cb * 8 + j;
        size_t zi = (size_t)b * CHW + (size_t)c * HW + p0 + p;
        float r = tile[c][p];
        float x = ze[zi];
        float d = r - x;
        err += d * d;
        out_zdl[zi] = r;
    }
    red[threadIdx.x] = err;
    __syncthreads();
    for (int o = 128; o; o >>= 1) {
        if (threadIdx.x < o) red[threadIdx.x] += red[threadIdx.x + o];
        __syncthreads();
    }
    if (threadIdx.x == 0) g_partial[blockIdx.x] = red[0];
}

// ---------------------------------------------------------------------------
// Kernel 6: deterministic loss reduction. loss = 1.25 * MSE
// ---------------------------------------------------------------------------
__global__ void k_loss(float* __restrict__ out_loss) {
    __shared__ float red[256];
    float s = 0.f;
    for (int i = threadIdx.x; i < 1024; i += 256) s += g_partial[i];
    red[threadIdx.x] = s;
    __syncthreads();
    for (int o = 128; o; o >>= 1) {
        if (threadIdx.x < o) red[threadIdx.x] += red[threadIdx.x + o];
        __syncthreads();
    }
    if (threadIdx.x == 0) out_loss[0] = 1.25f * red[0] / NUMEL;
}

// ---------------------------------------------------------------------------
extern "C" void kernel_launch(void* const* d_in, const int* in_sizes, int n_in,
                              void* d_out, int out_size) {
    const float* ze   = (const float*)d_in[0];
    const float* dict = (const float*)d_in[1];
    float* out = (float*)d_out;
    float* out_zdl  = out;
    float* out_loss = out + 2097152;
    float* out_sup  = out + 2097153;
    float* out_cf   = out + 2097153 + 163840;

    k_norm<<<2, 256>>>(dict);
    k_gram<<<NA, 128>>>();
    dim3 g(NA / 128, MS / 128);
    k_gemm<<<g, 256>>>(ze);
    k_omp<<<MS / 4, 128>>>(out_sup, out_cf);
    k_recon<<<MS / 32, 256>>>(ze, out_sup, out_cf, out_zdl);
    k_loss<<<1, 256>>>(out_loss);
}